// round 17
// baseline (speedup 1.0000x reference)
#include <cuda_runtime.h>
#include <cuda_bf16.h>
#include <mma.h>
#include <math.h>

using namespace nvcuda;

#define TT 512
#define BB 256
#define IND 256
#define HH 512
#define OUTD 64
#define NBLK 128
#define NTHR 512
#define WSH 1032
#define WSU 520
#define ASTR 136

// ---------------- device scratch (static allocations only) ----------------
__device__ __nv_bfloat16 g_Xs[(size_t)TT*BB*512];   // per row: [xhi(256) | xlo(256)]
// Split-bf16 activations, per row layout: [hi(512) | lo(512)]
__device__ __nv_bfloat16 g_Are[BB*1024];
__device__ __nv_bfloat16 g_Aim[BB*1024];
__device__ __nv_bfloat16 g_Amod[BB*1024];
__device__ float g_zre[BB*HH];
__device__ float g_gre[BB*HH];
__device__ float g_gim[BB*HH];
__device__ float g_gtau[BB*HH];
__device__ float g_gux[BB*HH];
__device__ float g_bias_re[HH];
__device__ float g_bias_im[HH];
__device__ float g_partials[NBLK];
__device__ int bar_cnt;
__device__ volatile unsigned bar_gen;
// fused scale reduction state (reset each launch in the prologue)
__device__ int g_scnt;
__device__ int g_sflag;
__device__ float g_scale;

__device__ __forceinline__ float sigf(float v) { return 1.0f / (1.0f + expf(-v)); }

__device__ __forceinline__ float clampf(float v, float lo, float hi) {
    return fminf(hi, fmaxf(lo, v));
}

// Atomic-counter grid barrier: all NBLK blocks resident (1 CTA/SM).
__device__ __forceinline__ void grid_barrier() {
    __syncthreads();
    if (threadIdx.x == 0) {
        unsigned g = bar_gen;
        __threadfence();
        if (atomicAdd(&bar_cnt, 1) == NBLK - 1) {
            bar_cnt = 0;
            __threadfence();
            bar_gen = g + 1;
        } else {
            while (bar_gen == g) { }
        }
        __threadfence();
    }
    __syncthreads();
}

__global__ void __launch_bounds__(NTHR, 1)
twistor_persistent(const float* __restrict__ x,
                   const float* __restrict__ W_real_w, const float* __restrict__ W_real_b,
                   const float* __restrict__ W_imag_w, const float* __restrict__ W_imag_b,
                   const float* __restrict__ U_w,      const float* __restrict__ U_b,
                   const float* __restrict__ W_tau_w,  const float* __restrict__ W_tau_b,
                   const float* __restrict__ mask_real,const float* __restrict__ mask_imag,
                   const float* __restrict__ tau_bias,
                   const float* __restrict__ b_real,   const float* __restrict__ b_imag,
                   const float* __restrict__ out_w,    const float* __restrict__ out_b,
                   float* __restrict__ y)
{
    extern __shared__ __align__(16) char dsmem[];
    __nv_bfloat16* sW = (__nv_bfloat16*)dsmem;      // 64 rows x WSH (or WSU)
    __nv_bfloat16* sA = sW + 64*WSH;                // 2 buffers of 64 x ASTR

    __shared__ float zsm[2][512];
    __shared__ float red[8][2][64];
    __shared__ float rbuf[16];
    __shared__ float s_scale;

    int tid = threadIdx.x;
    int bx  = blockIdx.x;
    int gtid = bx*NTHR + tid;
    const int NTOT = NBLK*NTHR;

    // ---------------- per-block GEMM tile mapping ------------------------
    int which = bx >> 5;
    int tile  = bx & 31;
    int m0    = (tile >> 3) << 6;
    int n0    = (tile & 7)  << 6;

    // ---------------- prologue ------------------------------------------
    if (gtid == 0) {
        g_scnt = 0;
        g_sflag = 0;
    }
    // Build this block's weight slice into pinned smem: [Wh | Wl] per row.
    if (which < 3) {
        for (int idx = tid; idx < 64*512; idx += NTHR) {
            int r = idx >> 9;
            int c = idx & 511;
            int grow = n0 + r;
            float wv;
            if (which == 0) {
                wv = W_real_w[grow*512 + c] * sigf(mask_real[grow*512 + c]);
            } else if (which == 1) {
                wv = W_imag_w[grow*512 + c] * sigf(mask_imag[grow*512 + c]);
            } else {
                wv = W_tau_w[grow*512 + c];
            }
            __nv_bfloat16 hb = __float2bfloat16_rn(wv);
            float hv = __bfloat162float(hb);
            __nv_bfloat16 lb = __float2bfloat16_rn(wv - hv);
            sW[r*WSH + c]       = hb;
            sW[r*WSH + 512 + c] = lb;
        }
    } else {
        for (int idx = tid; idx < 64*256; idx += NTHR) {
            int r = idx >> 8;
            int c = idx & 255;
            float wv = U_w[(n0 + r)*256 + c];
            __nv_bfloat16 hb = __float2bfloat16_rn(wv);
            float hv = __bfloat162float(hb);
            __nv_bfloat16 lb = __float2bfloat16_rn(wv - hv);
            sW[r*WSU + c]       = hb;
            sW[r*WSU + 256 + c] = lb;
        }
    }
    for (size_t i = gtid; i < (size_t)TT*BB*IND; i += NTOT) {
        size_t rr = i >> 8;
        int cc = (int)(i & 255);
        float wv = x[i];
        __nv_bfloat16 hb = __float2bfloat16_rn(wv);
        float hv = __bfloat162float(hb);
        __nv_bfloat16 lb = __float2bfloat16_rn(wv - hv);
        g_Xs[rr*512 + cc] = hb;
        g_Xs[rr*512 + 256 + cc] = lb;
    }
    {
        __nv_bfloat16 mh = __float2bfloat16_rn(1e-6f);
        float mhv = __bfloat162float(mh);
        __nv_bfloat16 ml = __float2bfloat16_rn(1e-6f - mhv);
        __nv_bfloat16 zb = __float2bfloat16_rn(0.0f);
        for (int i = gtid; i < BB*HH; i += NTOT) {
            int rr = i >> 9;
            int cc = i & 511;
            g_zre[i] = 0.0f;
            g_Are[rr*1024+cc] = zb;
            g_Are[rr*1024+512+cc] = zb;
            g_Aim[rr*1024+cc] = zb;
            g_Aim[rr*1024+512+cc] = zb;
            g_Amod[rr*1024+cc] = mh;
            g_Amod[rr*1024+512+cc] = ml;
        }
    }
    for (int i = gtid; i < HH; i += NTOT) {
        g_bias_re[i] = W_real_b[i] + U_b[i] + b_real[i];
        g_bias_im[i] = W_imag_b[i] + U_b[i] + b_imag[i];
    }
    grid_barrier();

    const __nv_bfloat16* Abase;
    float* C;
    int KP;
    int RSA;
    int WS;
    int WWRAP;
    int ASEG;
    if (which == 0) {
        Abase = g_Are;  C = g_gre;  KP = 1536; RSA = 1024; WS = WSH; WWRAP = 1024; ASEG = 512;
    } else if (which == 1) {
        Abase = g_Aim;  C = g_gim;  KP = 1536; RSA = 1024; WS = WSH; WWRAP = 1024; ASEG = 512;
    } else if (which == 2) {
        Abase = g_Amod; C = g_gtau; KP = 1536; RSA = 1024; WS = WSH; WWRAP = 1024; ASEG = 512;
    } else {
        Abase = g_Xs;   C = g_gux;  KP = 768;  RSA = 512;  WS = WSU; WWRAP = 512;  ASEG = 256;
    }
    int NC = KP >> 7;              // chunks of 128

    int lr   = tid >> 3;           // 0..63, one loader row per 8 threads
    int lc16 = (tid & 7) * 16;     // 2 consecutive uint4 per thread
    int wid = tid >> 5;            // 0..15
    int wm  = wid & 3;             // 16-row group
    int wn  = wid >> 2;            // 16-col group
    int aFragOff = (wm*16)*ASTR;
    const __nv_bfloat16* sWrow = sW + (wn*16)*WS;

    int oo  = tid & 63;
    int seg = tid >> 6;
    float ob = out_b[oo];

    // ---------------- per-thread persistent state (z in registers) --------
    int i2 = bx * 512 + tid;
    int h0 = (i2 & 255) * 2;
    float2 vbr  = *(const float2*)(&g_bias_re[h0]);
    float2 vbi  = *(const float2*)(&g_bias_im[h0]);
    float2 vwtb = *(const float2*)(&W_tau_b[h0]);
    float2 vtb  = *(const float2*)(&tau_bias[h0]);
    float zr0 = 0.0f;
    float zr1 = 0.0f;
    float zi0 = 0.0f;
    float zi1 = 0.0f;

    for (int t = 0; t < TT; t++) {
        // ================= phase A: split-bf16 wmma GEMM ===================
        {
            const __nv_bfloat16* Ag = Abase;
            if (which == 3) {
                Ag = g_Xs + (size_t)t*BB*512;
            }
            const __nv_bfloat16* aRow = Ag + (size_t)(m0+lr)*RSA + lc16;

            wmma::fragment<wmma::accumulator, 16, 16, 16, float> acc;
            wmma::fill_fragment(acc, 0.0f);

            // preload chunk 0 into smem buf0, chunk 1 into register slot B
            uint4 raA0;
            uint4 raA1;
            uint4 raB0;
            uint4 raB1;
            raA0 = *(const uint4*)(aRow);
            raA1 = *(const uint4*)(aRow + 8);
            *(uint4*)(&sA[lr*ASTR + lc16])     = raA0;
            *(uint4*)(&sA[lr*ASTR + lc16 + 8]) = raA1;
            {
                // kc = 128: stacked segments are [Ah | Ah | Al]
                int ac = (128 < WWRAP) ? (128 & (ASEG - 1)) : (128 - ASEG);
                raB0 = *(const uint4*)(aRow + ac);
                raB1 = *(const uint4*)(aRow + ac + 8);
            }
            __syncthreads();

            for (int ch = 0; ch < NC; ch += 2) {
                // even sub-iteration: compute buf0 holding chunk ch
                if (ch + 2 < NC) {
                    int kc = (ch + 2) << 7;
                    int ac = (kc < WWRAP) ? (kc & (ASEG - 1)) : (kc - ASEG);
                    raA0 = *(const uint4*)(aRow + ac);
                    raA1 = *(const uint4*)(aRow + ac + 8);
                }
                {
                    int kc = ch << 7;
                    int wOff = (kc < WWRAP) ? kc : (kc - WWRAP);
                    const __nv_bfloat16* sAc = sA + aFragOff;
                    const __nv_bfloat16* sWc = sWrow + wOff;
                    #pragma unroll
                    for (int q = 0; q < 8; q++) {
                        wmma::fragment<wmma::matrix_a, 16, 16, 16, __nv_bfloat16, wmma::row_major> fa;
                        wmma::fragment<wmma::matrix_b, 16, 16, 16, __nv_bfloat16, wmma::col_major> fb;
                        wmma::load_matrix_sync(fa, sAc + q*16, ASTR);
                        wmma::load_matrix_sync(fb, sWc + q*16, WS);
                        wmma::mma_sync(acc, fa, fb, acc);
                    }
                }
                // slot B holds chunk ch+1 (always valid: NC is even)
                *(uint4*)(&sA[8704 + lr*ASTR + lc16])     = raB0;
                *(uint4*)(&sA[8704 + lr*ASTR + lc16 + 8]) = raB1;
                __syncthreads();

                // odd sub-iteration: compute buf1 holding chunk ch+1
                if (ch + 3 < NC) {
                    int kc = (ch + 3) << 7;
                    int ac = (kc < WWRAP) ? (kc & (ASEG - 1)) : (kc - ASEG);
                    raB0 = *(const uint4*)(aRow + ac);
                    raB1 = *(const uint4*)(aRow + ac + 8);
                }
                {
                    int kc = (ch + 1) << 7;
                    int wOff = (kc < WWRAP) ? kc : (kc - WWRAP);
                    const __nv_bfloat16* sAc = sA + 8704 + aFragOff;
                    const __nv_bfloat16* sWc = sWrow + wOff;
                    #pragma unroll
                    for (int q = 0; q < 8; q++) {
                        wmma::fragment<wmma::matrix_a, 16, 16, 16, __nv_bfloat16, wmma::row_major> fa;
                        wmma::fragment<wmma::matrix_b, 16, 16, 16, __nv_bfloat16, wmma::col_major> fb;
                        wmma::load_matrix_sync(fa, sAc + q*16, ASTR);
                        wmma::load_matrix_sync(fb, sWc + q*16, WS);
                        wmma::mma_sync(acc, fa, fb, acc);
                    }
                }
                if (ch + 2 < NC) {
                    // slot A holds chunk ch+2
                    *(uint4*)(&sA[lr*ASTR + lc16])     = raA0;
                    *(uint4*)(&sA[lr*ASTR + lc16 + 8]) = raA1;
                    __syncthreads();
                }
            }

            float* Cout = C + (size_t)(m0 + wm*16)*512 + n0 + wn*16;
            wmma::store_matrix_sync(Cout, acc, 512, wmma::mem_row_major);
        }

        // ===== deferred readout of step t-1, done by the idle Ux blocks =====
        if (which == 3 && t > 0) {
            int bxu = tile;                  // 0..31 -> B rows [8*bxu, 8*bxu+8)
            float* zst  = (float*)(sW + 64*WSU);   // 8 x 512 floats
            float* redU = zst + 4096;              // seg x row x 64 floats
            __syncthreads();
            const float4* zsrc = (const float4*)(g_zre + (size_t)bxu*8*512);
            for (int i = tid; i < 1024; i += NTHR) {
                ((float4*)zst)[i] = zsrc[i];
            }
            __syncthreads();
            float acc0;
            float acc1;
            float acc2;
            float acc3;
            float acc4;
            float acc5;
            float acc6;
            float acc7;
            acc0 = 0.0f; acc1 = 0.0f; acc2 = 0.0f; acc3 = 0.0f;
            acc4 = 0.0f; acc5 = 0.0f; acc6 = 0.0f; acc7 = 0.0f;
            const float4* wrow = (const float4*)(out_w + (size_t)oo*512 + seg*64);
            #pragma unroll 8
            for (int k4 = 0; k4 < 16; k4++) {
                float4 wv = wrow[k4];
                int zb = seg*64 + k4*4;
                float4 z0 = *(const float4*)(zst + 0*512 + zb);
                float4 z1 = *(const float4*)(zst + 1*512 + zb);
                float4 z2 = *(const float4*)(zst + 2*512 + zb);
                float4 z3 = *(const float4*)(zst + 3*512 + zb);
                acc0 += wv.x*z0.x + wv.y*z0.y + wv.z*z0.z + wv.w*z0.w;
                acc1 += wv.x*z1.x + wv.y*z1.y + wv.z*z1.z + wv.w*z1.w;
                acc2 += wv.x*z2.x + wv.y*z2.y + wv.z*z2.z + wv.w*z2.w;
                acc3 += wv.x*z3.x + wv.y*z3.y + wv.z*z3.z + wv.w*z3.w;
                float4 z4 = *(const float4*)(zst + 4*512 + zb);
                float4 z5 = *(const float4*)(zst + 5*512 + zb);
                float4 z6 = *(const float4*)(zst + 6*512 + zb);
                float4 z7 = *(const float4*)(zst + 7*512 + zb);
                acc4 += wv.x*z4.x + wv.y*z4.y + wv.z*z4.z + wv.w*z4.w;
                acc5 += wv.x*z5.x + wv.y*z5.y + wv.z*z5.z + wv.w*z5.w;
                acc6 += wv.x*z6.x + wv.y*z6.y + wv.z*z6.z + wv.w*z6.w;
                acc7 += wv.x*z7.x + wv.y*z7.y + wv.z*z7.z + wv.w*z7.w;
            }
            redU[(seg*8 + 0)*64 + oo] = acc0;
            redU[(seg*8 + 1)*64 + oo] = acc1;
            redU[(seg*8 + 2)*64 + oo] = acc2;
            redU[(seg*8 + 3)*64 + oo] = acc3;
            redU[(seg*8 + 4)*64 + oo] = acc4;
            redU[(seg*8 + 5)*64 + oo] = acc5;
            redU[(seg*8 + 6)*64 + oo] = acc6;
            redU[(seg*8 + 7)*64 + oo] = acc7;
            __syncthreads();
            if (seg == 0) {
                #pragma unroll
                for (int r = 0; r < 8; r++) {
                    float yv = ob;
                    #pragma unroll
                    for (int s = 0; s < 8; s++) {
                        yv += redU[(s*8 + r)*64 + oo];
                    }
                    y[((size_t)(t-1)*BB + bxu*8 + r)*OUTD + oo] = yv;
                }
            }
        }
        grid_barrier();

        // ========== phase B: elementwise + fused scale sync + update =======
        float dre[2];
        float dimm[2];
        {
            float2 vre = ((const float2*)g_gre)[i2];
            float2 vim = ((const float2*)g_gim)[i2];
            float2 vta = ((const float2*)g_gtau)[i2];
            float2 vux = ((const float2*)g_gux)[i2];

            float lsum = 0.0f;
            {
                float dzr = vre.x + vux.x + vbr.x - zr0;
                float dzi = vim.x + vux.x + vbi.x - zi0;
                float tau = clampf(sigf(vta.x + vwtb.x) + vtb.x, 0.01f, 1.0f) + 1e-6f;
                float dr  = clampf(dzr / tau, -10.0f, 10.0f);
                float di  = clampf(dzi / tau, -10.0f, 10.0f);
                lsum += sqrtf(dr*dr + di*di + 1e-12f);
                dre[0] = dr;
                dimm[0] = di;
            }
            {
                float dzr = vre.y + vux.y + vbr.y - zr1;
                float dzi = vim.y + vux.y + vbi.y - zi1;
                float tau = clampf(sigf(vta.y + vwtb.y) + vtb.y, 0.01f, 1.0f) + 1e-6f;
                float dr  = clampf(dzr / tau, -10.0f, 10.0f);
                float di  = clampf(dzi / tau, -10.0f, 10.0f);
                lsum += sqrtf(dr*dr + di*di + 1e-12f);
                dre[1] = dr;
                dimm[1] = di;
            }
            #pragma unroll
            for (int off = 16; off > 0; off >>= 1) {
                lsum += __shfl_down_sync(0xFFFFFFFFu, lsum, off);
            }
            if ((tid & 31) == 0) {
                rbuf[tid >> 5] = lsum;
            }
            __syncthreads();
            if (tid == 0) {
                float s = 0.0f;
                #pragma unroll
                for (int ww = 0; ww < 16; ww++) {
                    s += rbuf[ww];
                }
                g_partials[bx] = s;
                __threadfence();
                int old = atomicAdd(&g_scnt, 1);
                if (old == (t + 1) * NBLK - 1) {
                    float tot = 0.0f;
                    for (int b = 0; b < NBLK; b++) {
                        tot += ((volatile float*)g_partials)[b];
                    }
                    float mean = tot / (float)(BB * HH);
                    float sc = 1.0f;
                    if (mean > 5.0f) {
                        sc = 5.0f / (mean + 1e-6f);
                    }
                    g_scale = sc;
                    __threadfence();
                    *((volatile int*)&g_sflag) = t + 1;
                }
                while (*((volatile int*)&g_sflag) < t + 1) { }
                s_scale = *((volatile float*)&g_scale);
            }
            __syncthreads();
        }
        {
            float scale = s_scale;

            int flat0 = i2 * 2;
            int arw   = flat0 >> 9;
            int acl   = flat0 & 511;
            int abase = arw*1024 + acl;

            zr0 = clampf(zr0 + 0.1f * scale * dre[0],  -100.0f, 100.0f);
            zr1 = clampf(zr1 + 0.1f * scale * dre[1],  -100.0f, 100.0f);
            zi0 = clampf(zi0 + 0.1f * scale * dimm[0], -100.0f, 100.0f);
            zi1 = clampf(zi1 + 0.1f * scale * dimm[1], -100.0f, 100.0f);

            float ar0 = tanhf(zr0);
            float ar1 = tanhf(zr1);
            float ai0 = tanhf(zi0);
            float ai1 = tanhf(zi1);
            float am0 = sqrtf(zr0*zr0 + zi0*zi0 + 1e-12f);
            float am1 = sqrtf(zr1*zr1 + zi1*zi1 + 1e-12f);

            __nv_bfloat162 ph;
            __nv_bfloat162 pl;
            float hv0;
            float hv1;
            ph.x = __float2bfloat16_rn(ar0);
            ph.y = __float2bfloat16_rn(ar1);
            hv0 = __bfloat162float(ph.x);
            hv1 = __bfloat162float(ph.y);
            pl.x = __float2bfloat16_rn(ar0 - hv0);
            pl.y = __float2bfloat16_rn(ar1 - hv1);
            *(__nv_bfloat162*)(&g_Are[abase])     = ph;
            *(__nv_bfloat162*)(&g_Are[abase+512]) = pl;
            ph.x = __float2bfloat16_rn(ai0);
            ph.y = __float2bfloat16_rn(ai1);
            hv0 = __bfloat162float(ph.x);
            hv1 = __bfloat162float(ph.y);
            pl.x = __float2bfloat16_rn(ai0 - hv0);
            pl.y = __float2bfloat16_rn(ai1 - hv1);
            *(__nv_bfloat162*)(&g_Aim[abase])     = ph;
            *(__nv_bfloat162*)(&g_Aim[abase+512]) = pl;
            ph.x = __float2bfloat16_rn(am0);
            ph.y = __float2bfloat16_rn(am1);
            hv0 = __bfloat162float(ph.x);
            hv1 = __bfloat162float(ph.y);
            pl.x = __float2bfloat16_rn(am0 - hv0);
            pl.y = __float2bfloat16_rn(am1 - hv1);
            *(__nv_bfloat162*)(&g_Amod[abase])     = ph;
            *(__nv_bfloat162*)(&g_Amod[abase+512]) = pl;

            float2 vz;
            vz.x = zr0;
            vz.y = zr1;
            ((float2*)g_zre)[i2] = vz;
        }
        grid_barrier();
    }

    // ---------------- epilogue: readout of the final step ------------------
    {
        float* zst2 = &zsm[0][0];
        const float4* zsrc = (const float4*)(g_zre + (size_t)bx*1024);
        for (int i = tid; i < 256; i += NTHR) {
            ((float4*)zst2)[i] = zsrc[i];
        }
        __syncthreads();
        float acc0 = 0.0f;
        float acc1 = 0.0f;
        const float4* wrow = (const float4*)(out_w + (size_t)oo*512 + seg*64);
        #pragma unroll 16
        for (int k4 = 0; k4 < 16; k4++) {
            float4 wv = wrow[k4];
            float4 z0 = *(const float4*)(zst2 + seg*64 + k4*4);
            float4 z1 = *(const float4*)(zst2 + 512 + seg*64 + k4*4);
            acc0 += wv.x*z0.x + wv.y*z0.y + wv.z*z0.z + wv.w*z0.w;
            acc1 += wv.x*z1.x + wv.y*z1.y + wv.z*z1.z + wv.w*z1.w;
        }
        red[seg][0][oo] = acc0;
        red[seg][1][oo] = acc1;
        __syncthreads();
        if (seg == 0) {
            #pragma unroll
            for (int r = 0; r < 2; r++) {
                float yv = ob;
                #pragma unroll
                for (int s = 0; s < 8; s++) {
                    yv += red[s][r][oo];
                }
                y[((size_t)(TT-1)*BB + bx*2 + r)*OUTD + oo] = yv;
            }
        }
    }
}

// ---------------- host launcher (graph-capturable, single node) ------------
extern "C" void kernel_launch(void* const* d_in, const int* in_sizes, int n_in,
                              void* d_out, int out_size)
{
    const float* x         = (const float*)d_in[0];
    const float* W_real_w  = (const float*)d_in[1];
    const float* W_real_b  = (const float*)d_in[2];
    const float* W_imag_w  = (const float*)d_in[3];
    const float* W_imag_b  = (const float*)d_in[4];
    const float* U_w       = (const float*)d_in[5];
    const float* U_b       = (const float*)d_in[6];
    const float* W_tau_w   = (const float*)d_in[7];
    const float* W_tau_b   = (const float*)d_in[8];
    const float* mask_real = (const float*)d_in[9];
    const float* mask_imag = (const float*)d_in[10];
    const float* tau_bias  = (const float*)d_in[11];
    const float* b_real    = (const float*)d_in[12];
    const float* b_imag    = (const float*)d_in[13];
    const float* out_w     = (const float*)d_in[14];
    const float* out_b     = (const float*)d_in[15];
    float* y = (float*)d_out;

    // dynamic smem: pinned weight slice (64 x WSH bf16) + A double buffer
    int dyn_smem = (64*WSH + 2*64*ASTR) * (int)sizeof(__nv_bfloat16);
    cudaFuncSetAttribute(twistor_persistent,
                         cudaFuncAttributeMaxDynamicSharedMemorySize, dyn_smem);
    twistor_persistent<<<NBLK, NTHR, dyn_smem>>>(x, W_real_w, W_real_b, W_imag_w, W_imag_b,
                                                 U_w, U_b, W_tau_w, W_tau_b,
                                                 mask_real, mask_imag, tau_bias,
                                                 b_real, b_imag, out_w, out_b, y);
}